// round 1
// baseline (speedup 1.0000x reference)
#include <cuda_runtime.h>

#define Nn 128
#define Dd 512
#define NPAIR 8128            // C(128,2)
#define NTRI  341376          // C(128,3)
#define NROWS (Nn + NPAIR + NTRI)   // 349632
#define EPS   32.0f
#define SHARP 10.0f

__device__ float    g_sq[Nn];
__device__ float    g_d[Nn * Nn];
__device__ float    g_pval[NPAIR];
__device__ unsigned g_pij[NPAIR];
__device__ unsigned g_tri[NTRI];

// --- row squared norms ---------------------------------------------------
__global__ void k_sq(const float* __restrict__ W) {
    int i = threadIdx.x;
    const float4* w = reinterpret_cast<const float4*>(W + (size_t)i * Dd);
    float s = 0.f;
#pragma unroll 8
    for (int k = 0; k < Dd / 4; k++) {
        float4 a = w[k];
        s += a.x * a.x;
        s += a.y * a.y;
        s += a.z * a.z;
        s += a.w * a.w;
    }
    g_sq[i] = s;
}

// --- pairwise distances: d = sqrt(max(sq_i + sq_j - 2*dot, 0)) -----------
__global__ void k_dist(const float* __restrict__ W) {
    int i = blockIdx.x, j = threadIdx.x;
    __shared__ float4 wi[Dd / 4];
    const float4* wg = reinterpret_cast<const float4*>(W + (size_t)i * Dd);
    for (int k = threadIdx.x; k < Dd / 4; k += blockDim.x) wi[k] = wg[k];
    __syncthreads();
    const float4* wj = reinterpret_cast<const float4*>(W + (size_t)j * Dd);
    float dot = 0.f;
#pragma unroll 8
    for (int k = 0; k < Dd / 4; k++) {
        float4 a = wi[k], b = wj[k];
        dot += a.x * b.x;
        dot += a.y * b.y;
        dot += a.z * b.z;
        dot += a.w * b.w;
    }
    float d2 = g_sq[i] + g_sq[j] - 2.f * dot;
    g_d[i * Nn + j] = sqrtf(fmaxf(d2, 0.f));
}

// --- pair table: packed (i,j) + sigmoid value -----------------------------
__global__ void k_pairs() {
    int i = blockIdx.x, j = threadIdx.x;
    if (j <= i) return;
    int p = i * (Nn - 1) - i * (i - 1) / 2 + (j - i - 1);
    float d = g_d[i * Nn + j];
    float val = 1.f / (1.f + __expf(0.f) * 0.f + expf(-SHARP * (EPS - d)));
    g_pval[p] = val;
    g_pij[p]  = (unsigned)i | ((unsigned)j << 8);
}

// --- triple table: packed (i,j,k) + cond bit ------------------------------
__device__ __forceinline__ int C3(int x) { return x * (x - 1) * (x - 2) / 6; }
__device__ __forceinline__ int T2(int x) { return x * (x + 1) / 2; }

__global__ void k_tri() {
    int i = blockIdx.x, j = threadIdx.x;
    if (j <= i || j >= Nn - 1) return;
    int start = C3(Nn) - C3(Nn - i) + T2(Nn - 2 - i) - T2(Nn - j - 1);
    bool aij = g_d[i * Nn + j] <= EPS;
    unsigned base = (unsigned)i | ((unsigned)j << 8);
    for (int k = j + 1; k < Nn; k++) {
        bool c = aij && (g_d[j * Nn + k] <= EPS) && (g_d[i * Nn + k] <= EPS);
        g_tri[start + (k - j - 1)] = base | ((unsigned)k << 16) | (c ? (1u << 24) : 0u);
    }
}

// --- output fill: one thread per float4 (4 columns of one row) ------------
__device__ __forceinline__ void setcol(float4& v, int col, int c0, float val) {
    if (col == c0)          v.x = val;
    else if (col == c0 + 1) v.y = val;
    else if (col == c0 + 2) v.z = val;
    else if (col == c0 + 3) v.w = val;
}

__global__ void __launch_bounds__(256) k_fill(float4* __restrict__ out) {
    int idx = blockIdx.x * 256 + threadIdx.x;   // < NROWS * 32
    int r  = idx >> 5;          // row
    int cg = idx & 31;          // float4 index within row
    int c0 = cg << 2;           // first column of this float4
    float4 v = make_float4(0.f, 0.f, 0.f, 0.f);

    if (r < Nn) {
        setcol(v, r, c0, 1.0f);
    } else if (r < Nn + NPAIR) {
        int p = r - Nn;
        unsigned u = g_pij[p];
        float val = g_pval[p];
        int i = u & 255, j = (u >> 8) & 255;
        setcol(v, i, c0, val);
        setcol(v, j, c0, val);
    } else {
        int t = r - Nn - NPAIR;
        unsigned u = g_tri[t];
        float val = (u >> 24) ? 1.0f : 0.0f;
        int i = u & 255, j = (u >> 8) & 255, k = (u >> 16) & 255;
        setcol(v, i, c0, val);
        setcol(v, j, c0, val);
        setcol(v, k, c0, val);
    }
    out[idx] = v;
}

extern "C" void kernel_launch(void* const* d_in, const int* in_sizes, int n_in,
                              void* d_out, int out_size) {
    const float* W = (const float*)d_in[0];
    float4* out = (float4*)d_out;

    k_sq<<<1, Nn>>>(W);
    k_dist<<<Nn, Nn>>>(W);
    k_pairs<<<Nn, Nn>>>();
    k_tri<<<Nn, Nn>>>();

    int total4 = NROWS * 32;                 // 11,188,224 float4 stores
    k_fill<<<total4 / 256, 256>>>(out);      // 43,704 blocks, exact cover
}

// round 2
// speedup vs baseline: 1.0169x; 1.0169x over previous
#include <cuda_runtime.h>

#define Nn 128
#define Dd 512
#define NPAIR 8128            // C(128,2)
#define NTRI  341376          // C(128,3)
#define NROWS (Nn + NPAIR + NTRI)   // 349632
#define EPS   32.0f
#define SHARP 10.0f

__device__ float    g_sq[Nn];
__device__ float    g_d[Nn * Nn];
__device__ float    g_pval[NPAIR];
__device__ unsigned g_pij[NPAIR];
__device__ unsigned g_tri[NTRI];

// --- row squared norms ---------------------------------------------------
__global__ void k_sq(const float* __restrict__ W) {
    int i = threadIdx.x;
    const float4* w = reinterpret_cast<const float4*>(W + (size_t)i * Dd);
    float s = 0.f;
#pragma unroll 8
    for (int k = 0; k < Dd / 4; k++) {
        float4 a = w[k];
        s += a.x * a.x;
        s += a.y * a.y;
        s += a.z * a.z;
        s += a.w * a.w;
    }
    g_sq[i] = s;
}

// --- pairwise distances: d = sqrt(max(sq_i + sq_j - 2*dot, 0)) -----------
__global__ void k_dist(const float* __restrict__ W) {
    int i = blockIdx.x, j = threadIdx.x;
    __shared__ float4 wi[Dd / 4];
    const float4* wg = reinterpret_cast<const float4*>(W + (size_t)i * Dd);
    for (int k = threadIdx.x; k < Dd / 4; k += blockDim.x) wi[k] = wg[k];
    __syncthreads();
    const float4* wj = reinterpret_cast<const float4*>(W + (size_t)j * Dd);
    float dot = 0.f;
#pragma unroll 8
    for (int k = 0; k < Dd / 4; k++) {
        float4 a = wi[k], b = wj[k];
        dot += a.x * b.x;
        dot += a.y * b.y;
        dot += a.z * b.z;
        dot += a.w * b.w;
    }
    float d2 = g_sq[i] + g_sq[j] - 2.f * dot;
    g_d[i * Nn + j] = sqrtf(fmaxf(d2, 0.f));
}

// --- pair table: packed (i,j) + sigmoid value -----------------------------
__global__ void k_pairs() {
    int i = blockIdx.x, j = threadIdx.x;
    if (j <= i) return;
    int p = i * (Nn - 1) - i * (i - 1) / 2 + (j - i - 1);
    float d = g_d[i * Nn + j];
    float val = 1.f / (1.f + __expf(0.f) * 0.f + expf(-SHARP * (EPS - d)));
    g_pval[p] = val;
    g_pij[p]  = (unsigned)i | ((unsigned)j << 8);
}

// --- triple table: packed (i,j,k) + cond bit ------------------------------
__device__ __forceinline__ int C3(int x) { return x * (x - 1) * (x - 2) / 6; }
__device__ __forceinline__ int T2(int x) { return x * (x + 1) / 2; }

__global__ void k_tri() {
    int i = blockIdx.x, j = threadIdx.x;
    if (j <= i || j >= Nn - 1) return;
    int start = C3(Nn) - C3(Nn - i) + T2(Nn - 2 - i) - T2(Nn - j - 1);
    bool aij = g_d[i * Nn + j] <= EPS;
    unsigned base = (unsigned)i | ((unsigned)j << 8);
    for (int k = j + 1; k < Nn; k++) {
        bool c = aij && (g_d[j * Nn + k] <= EPS) && (g_d[i * Nn + k] <= EPS);
        g_tri[start + (k - j - 1)] = base | ((unsigned)k << 16) | (c ? (1u << 24) : 0u);
    }
}

// --- output fill: one thread per float4 (4 columns of one row) ------------
__device__ __forceinline__ void setcol(float4& v, int col, int c0, float val) {
    if (col == c0)          v.x = val;
    else if (col == c0 + 1) v.y = val;
    else if (col == c0 + 2) v.z = val;
    else if (col == c0 + 3) v.w = val;
}

__global__ void __launch_bounds__(256) k_fill(float4* __restrict__ out) {
    int idx = blockIdx.x * 256 + threadIdx.x;   // < NROWS * 32
    int r  = idx >> 5;          // row
    int cg = idx & 31;          // float4 index within row
    int c0 = cg << 2;           // first column of this float4
    float4 v = make_float4(0.f, 0.f, 0.f, 0.f);

    if (r < Nn) {
        setcol(v, r, c0, 1.0f);
    } else if (r < Nn + NPAIR) {
        int p = r - Nn;
        unsigned u = g_pij[p];
        float val = g_pval[p];
        int i = u & 255, j = (u >> 8) & 255;
        setcol(v, i, c0, val);
        setcol(v, j, c0, val);
    } else {
        int t = r - Nn - NPAIR;
        unsigned u = g_tri[t];
        float val = (u >> 24) ? 1.0f : 0.0f;
        int i = u & 255, j = (u >> 8) & 255, k = (u >> 16) & 255;
        setcol(v, i, c0, val);
        setcol(v, j, c0, val);
        setcol(v, k, c0, val);
    }
    out[idx] = v;
}

extern "C" void kernel_launch(void* const* d_in, const int* in_sizes, int n_in,
                              void* d_out, int out_size) {
    const float* W = (const float*)d_in[0];
    float4* out = (float4*)d_out;

    k_sq<<<1, Nn>>>(W);
    k_dist<<<Nn, Nn>>>(W);
    k_pairs<<<Nn, Nn>>>();
    k_tri<<<Nn, Nn>>>();

    int total4 = NROWS * 32;                 // 11,188,224 float4 stores
    k_fill<<<total4 / 256, 256>>>(out);      // 43,704 blocks, exact cover
}